// round 13
// baseline (speedup 1.0000x reference)
#include <cuda_runtime.h>
#include <math.h>

#define Bn 1024
#define Tn 512
#define KK 48
#define NEG (-10000.0f)
#define SSTART 46
#define SSTOP  47
#define BPB 8
#define NTHREADS (BPB * KK)   // 384
#define NBLK (Bn / BPB)       // 128

// Viterbi value history: v ENTERING each step t, per (b, t, s).  ~100 MB scratch.
__device__ float vbuf_g[(size_t)Bn * Tn * KK];

__global__ void __launch_bounds__(NTHREADS, 1)
crf_fused_kernel(const float* __restrict__ feats,
                 const float* __restrict__ trans,
                 const int*   __restrict__ tags,
                 float*       __restrict__ out)
{
    __shared__ __align__(16) float2 eav[BPB][KK];  // (exp(alpha-m), v) interleaved
    __shared__ float trM[KK * KK];                 // masked transitions
    __shared__ float a0sh[BPB];                    // published alpha[0]
    __shared__ float msh[BPB];                     // running normalizer
    __shared__ float gbuf[BPB][KK];                // gold partials
    __shared__ int   blast[BPB];                   // best last tag

    const int tid = threadIdx.x;
    const int bl  = tid / KK;      // batch-in-block
    const int s   = tid % KK;      // owned next-state
    const int b   = blockIdx.x * BPB + bl;

    // Masked transition matrix: trans[next,prev]; row START and col STOP -> NEG
    for (int idx = tid; idx < KK * KK; idx += NTHREADS) {
        int n = idx / KK, p = idx % KK;
        float v = trans[idx];
        if (n == SSTART) v = NEG;
        if (p == SSTOP)  v = NEG;
        trM[idx] = v;
    }
    __syncthreads();

    // Per-thread rows in registers
    float Erow[KK], Trow[KK];
#pragma unroll
    for (int i = 0; i < KK; i++) {
        float tv = trM[s * KK + i];
        Trow[i] = tv;
        Erow[i] = __expf(tv);      // exp(-10000) underflows to exactly 0
    }
    const float tstop = trM[SSTOP * KK + s];

    // Gold score partials (strided over t)
    const float* fb = feats + (size_t)b * Tn * KK;
    const int*   tb = tags  + (size_t)b * Tn;
    {
        float gp = 0.0f;
        for (int t = s; t < Tn; t += KK) {
            int tg = tb[t];
            int pv = (t == 0) ? SSTART : tb[t - 1];
            gp += fb[(size_t)t * KK + tg] + trM[tg * KK + pv];
        }
        gbuf[bl][s] = gp;
    }

    // Init: alpha = NEG except START=0 (exp(alpha-0): START->1, else 0); v likewise
    eav[bl][s] = make_float2(s == SSTART ? 1.0f : 0.0f,
                             s == SSTART ? 0.0f : NEG);
    if (s == 0) msh[bl] = 0.0f;

    float alpha = 0.0f;
    float v = (s == SSTART) ? 0.0f : NEG;   // value ENTERING step t (t=0: init)

    const float* fptr = fb + s;
    float* vrow = vbuf_g + (size_t)b * Tn * KK + s;
    float femit = fptr[0];

#pragma unroll 1
    for (int t = 0; t < Tn; t++) {
        __syncthreads();
        const float m    = msh[bl];
        const float emit = femit;
        const float* nxt = fptr + KK;
        femit = (t < Tn - 1) ? nxt[0] : 0.0f;
        fptr = nxt;

        vrow[(size_t)t * KK] = v;          // ENTRY v for backtrace recompute (coalesced)

        // 24 float4 loads over interleaved (e,v) pairs; 8 independent chains.
        // Max is exact (no rounding) -> no index tracking, any merge order OK.
        const float4* ev4 = (const float4*)&eav[bl][0];   // ev4[i] = (e_{2i}, v_{2i}, e_{2i+1}, v_{2i+1})
        float sa0 = 0.f, sa1 = 0.f, sa2 = 0.f, sa3 = 0.f;
        float sb0 = 0.f, sb1 = 0.f, sb2 = 0.f, sb3 = 0.f;
        float ma0 = -INFINITY, ma1 = -INFINITY, ma2 = -INFINITY, ma3 = -INFINITY;
        float mb0 = -INFINITY, mb1 = -INFINITY, mb2 = -INFINITY, mb3 = -INFINITY;
#pragma unroll
        for (int j = 0; j < 6; j++) {
            {
                float4 a = ev4[j];                 // prevs 2j, 2j+1
                sa0 = fmaf(Erow[2 * j],     a.x, sa0);
                sb0 = fmaf(Erow[2 * j + 1], a.z, sb0);
                ma0 = fmaxf(ma0, a.y + Trow[2 * j]);
                mb0 = fmaxf(mb0, a.w + Trow[2 * j + 1]);
            }
            {
                float4 a = ev4[6 + j];             // prevs 12+2j, 13+2j
                sa1 = fmaf(Erow[12 + 2 * j], a.x, sa1);
                sb1 = fmaf(Erow[13 + 2 * j], a.z, sb1);
                ma1 = fmaxf(ma1, a.y + Trow[12 + 2 * j]);
                mb1 = fmaxf(mb1, a.w + Trow[13 + 2 * j]);
            }
            {
                float4 a = ev4[12 + j];            // prevs 24+2j, 25+2j
                sa2 = fmaf(Erow[24 + 2 * j], a.x, sa2);
                sb2 = fmaf(Erow[25 + 2 * j], a.z, sb2);
                ma2 = fmaxf(ma2, a.y + Trow[24 + 2 * j]);
                mb2 = fmaxf(mb2, a.w + Trow[25 + 2 * j]);
            }
            {
                float4 a = ev4[18 + j];            // prevs 36+2j, 37+2j
                sa3 = fmaf(Erow[36 + 2 * j], a.x, sa3);
                sb3 = fmaf(Erow[37 + 2 * j], a.z, sb3);
                ma3 = fmaxf(ma3, a.y + Trow[36 + 2 * j]);
                mb3 = fmaxf(mb3, a.w + Trow[37 + 2 * j]);
            }
        }
        const float ssum = ((sa0 + sb0) + (sa1 + sb1)) + ((sa2 + sb2) + (sa3 + sb3));
        const float best = fmaxf(fmaxf(fmaxf(ma0, mb0), fmaxf(ma1, mb1)),
                                 fmaxf(fmaxf(ma2, mb2), fmaxf(ma3, mb3)));

        alpha = emit + m + __logf(ssum);   // log(0) -> -inf for START row: correct
        v     = best + emit;               // bit-identical value to reference

        if (s == 0) a0sh[bl] = alpha;
        __syncthreads();
        const float m2 = a0sh[bl];
        eav[bl][s] = make_float2(__expf(alpha - m2), v);
        if (s == 0) msh[bl] = m2;
    }

    __syncthreads();
    // Terminal terms
    eav[bl][s] = make_float2(alpha + tstop, v + tstop);
    __syncthreads();

    if (s == 0) {
        float gold = 0.0f;
        for (int i = 0; i < KK; i++) gold += gbuf[bl][i];
        gold += trM[SSTOP * KK + tb[Tn - 1]];

        float mz = -INFINITY, bv = -INFINITY;
        int best_last = 0;
        for (int i = 0; i < KK; i++) {
            float2 e = eav[bl][i];
            if (e.x > mz) mz = e.x;
            if (e.y > bv) { bv = e.y; best_last = i; }   // first-index tie-break
        }
        float sz = 0.0f;
        for (int i = 0; i < KK; i++)
            sz += __expf(eav[bl][i].x - mz);
        const float logZ = mz + __logf(sz);

        out[b]      = logZ - gold;   // nll
        out[Bn + b] = bv;            // path_score
        blast[bl]   = best_last;
        out[2 * (size_t)Bn + (size_t)b * Tn + (Tn - 1)] = (float)best_last;
    }
    __syncthreads();

    // ---- Backtrace: one warp per batch, recompute backpointers from vbuf ----
    const int w = tid >> 5;
    const int lane = tid & 31;
    if (w < BPB) {
        const int bb = blockIdx.x * BPB + w;
        const float* vb = vbuf_g + (size_t)bb * Tn * KK;
        float* pout = out + 2 * (size_t)Bn + (size_t)bb * Tn;
        int cur = blast[w];

        // depth-4 prefetch ring over rows t = 511..508
        float ra[4], rb[4];
#pragma unroll
        for (int k = 0; k < 4; k++) {
            int tt = Tn - 1 - k;
            ra[k] = vb[(size_t)tt * KK + lane];
            rb[k] = (lane < 16) ? vb[(size_t)tt * KK + 32 + lane] : -INFINITY;
        }

        int t = Tn - 1;
#pragma unroll 1
        for (int iter = 0; iter < 128; iter++) {
#pragma unroll
            for (int k = 0; k < 4; k++) {
                if (t >= 1) {
                    // bp(t,cur) = first-argmax_prev( v_entry[t][prev] + trM[cur][prev] )
                    float val = ra[k] + trM[cur * KK + lane];
                    int   idx = lane;
                    if (lane < 16) {
                        float vB = rb[k] + trM[cur * KK + 32 + lane];
                        if (vB > val) { val = vB; idx = lane + 32; }  // tie -> lower idx
                    }
#pragma unroll
                    for (int off = 16; off >= 1; off >>= 1) {
                        float ov = __shfl_xor_sync(0xffffffffu, val, off);
                        int   oi = __shfl_xor_sync(0xffffffffu, idx, off);
                        if (ov > val || (ov == val && oi < idx)) { val = ov; idx = oi; }
                    }
                    cur = idx;
                    if (lane == 0) pout[t - 1] = (float)cur;

                    const int tn = t - 4;            // refill this ring slot
                    if (tn >= 1) {
                        ra[k] = vb[(size_t)tn * KK + lane];
                        if (lane < 16) rb[k] = vb[(size_t)tn * KK + 32 + lane];
                    }
                    t--;
                }
            }
        }
    }
}

extern "C" void kernel_launch(void* const* d_in, const int* in_sizes, int n_in,
                              void* d_out, int out_size)
{
    const float* feats = (const float*)d_in[0];
    const float* trans = (const float*)d_in[1];
    const int*   tags  = (const int*)d_in[2];
    float* out = (float*)d_out;

    crf_fused_kernel<<<NBLK, NTHREADS>>>(feats, trans, tags, out);
}

// round 15
// speedup vs baseline: 2.0885x; 2.0885x over previous
#include <cuda_runtime.h>
#include <math.h>

#define Bn 1024
#define Tn 512
#define KK 48
#define NEG (-10000.0f)
#define SSTART 46
#define SSTOP  47
#define BPB 8
#define NTHREADS (BPB * KK)   // 384
#define NBLK (Bn / BPB)       // 128

// Dynamic shared memory layout (bytes):
//   bp   : BPB*Tn*KK  uint8          = 196608
//   bufE : 2*BPB*KK   float (16B al) =   3072
//   bufV : 2*BPB*KK   float          =   3072
//   trM  : KK*KK      float          =   9216
//   normU: 2*BPB, normP: 2*BPB       =    128
//   gbuf : BPB*KK     float          =   1536
#define SMEM_BP    (BPB * Tn * KK)
#define SMEM_BYTES (SMEM_BP + 2*BPB*KK*4 + 2*BPB*KK*4 + KK*KK*4 + 4*BPB*4 + BPB*KK*4)

extern __shared__ unsigned char s_raw[];

__global__ void __launch_bounds__(NTHREADS, 1)
crf_fused_kernel(const float* __restrict__ feats,
                 const float* __restrict__ trans,
                 const int*   __restrict__ tags,
                 float*       __restrict__ out)
{
    unsigned char* bp = s_raw;                                  // [BPB][Tn][KK]
    float* bufE  = (float*)(s_raw + SMEM_BP);                   // [2][BPB][KK] exp(alpha-norm)
    float* bufV  = bufE + 2 * BPB * KK;                         // [2][BPB][KK] viterbi v
    float* trM   = bufV + 2 * BPB * KK;                         // [KK*KK]
    float* normU = trM + KK * KK;                               // [2][BPB] normalizer of bufE[p]
    float* normP = normU + 2 * BPB;                             // [2][BPB] published alpha[0]
    float* gbuf  = normP + 2 * BPB;                             // [BPB*KK]

    const int tid = threadIdx.x;
    const int bl  = tid / KK;      // batch-in-block
    const int s   = tid % KK;      // owned next-state
    const int b   = blockIdx.x * BPB + bl;

    // Masked transition matrix: trans[next,prev]; row START and col STOP -> NEG
    for (int idx = tid; idx < KK * KK; idx += NTHREADS) {
        int n = idx / KK, p = idx % KK;
        float v = trans[idx];
        if (n == SSTART) v = NEG;
        if (p == SSTOP)  v = NEG;
        trM[idx] = v;
    }
    __syncthreads();

    // Per-thread rows in registers
    float Erow[KK], Trow[KK];
#pragma unroll
    for (int i = 0; i < KK; i++) {
        float tv = trM[s * KK + i];
        Trow[i] = tv;
        Erow[i] = __expf(tv);      // exp(-10000) underflows to exactly 0
    }
    const float tstop = trM[SSTOP * KK + s];

    // Gold score partials (strided over t)
    const float* fb = feats + (size_t)b * Tn * KK;
    const int*   tb = tags  + (size_t)b * Tn;
    {
        float gp = 0.0f;
        for (int t = s; t < Tn; t += KK) {
            int tg = tb[t];
            int pv = (t == 0) ? SSTART : tb[t - 1];
            gp += fb[(size_t)t * KK + tg] + trM[tg * KK + pv];
        }
        gbuf[bl * KK + s] = gp;
    }

    // Init parity 0: alpha = NEG except START=0 -> exp(alpha-0): {START:1, else 0}
    bufE[bl * KK + s] = (s == SSTART) ? 1.0f : 0.0f;
    bufV[bl * KK + s] = (s == SSTART) ? 0.0f : NEG;
    if (s == 0) { normU[bl] = 0.0f; normP[bl] = 0.0f; }

    float alpha = 0.0f, v = 0.0f;
    const float* fptr = fb + s;
    float femit = fptr[0];
    unsigned char* bprow = bp + (size_t)(bl * Tn) * KK + s;

#pragma unroll 1
    for (int t = 0; t < Tn; t++) {
        __syncthreads();                       // single barrier per step
        const int p = t & 1;
        const int q = p ^ 1;
        const float M = normU[p * BPB + bl];   // normalizer of bufE[p]
        const float W = normP[p * BPB + bl];   // normalizer for writing bufE[q]
        const float emit = femit;
        const float* nxt = fptr + KK;
        femit = (t < Tn - 1) ? nxt[0] : 0.0f;
        fptr = nxt;

        const float4* E4 = (const float4*)(bufE + (p * BPB + bl) * KK);  // 12 float4
        const float4* V4 = (const float4*)(bufV + (p * BPB + bl) * KK);

        // 4 contiguous chains of 12 (contiguity preserves first-index argmax tie-break)
        float ss0 = 0.f, ss1 = 0.f, ss2 = 0.f, ss3 = 0.f;
        float bst0 = -INFINITY, bst1 = -INFINITY, bst2 = -INFINITY, bst3 = -INFINITY;
        int   bi0 = 0, bi1 = 12, bi2 = 24, bi3 = 36;
#pragma unroll
        for (int c = 0; c < 3; c++) {          // 3 float4s per chain of 12
            {
                float4 e = E4[c], w = V4[c];
                ss0 = fmaf(Erow[4*c+0], e.x, ss0);
                ss0 = fmaf(Erow[4*c+1], e.y, ss0);
                ss0 = fmaf(Erow[4*c+2], e.z, ss0);
                ss0 = fmaf(Erow[4*c+3], e.w, ss0);
                float c0 = w.x + Trow[4*c+0]; if (c0 > bst0) { bst0 = c0; bi0 = 4*c+0; }
                float c1 = w.y + Trow[4*c+1]; if (c1 > bst0) { bst0 = c1; bi0 = 4*c+1; }
                float c2 = w.z + Trow[4*c+2]; if (c2 > bst0) { bst0 = c2; bi0 = 4*c+2; }
                float c3 = w.w + Trow[4*c+3]; if (c3 > bst0) { bst0 = c3; bi0 = 4*c+3; }
            }
            {
                float4 e = E4[3+c], w = V4[3+c];
                ss1 = fmaf(Erow[12+4*c+0], e.x, ss1);
                ss1 = fmaf(Erow[12+4*c+1], e.y, ss1);
                ss1 = fmaf(Erow[12+4*c+2], e.z, ss1);
                ss1 = fmaf(Erow[12+4*c+3], e.w, ss1);
                float c0 = w.x + Trow[12+4*c+0]; if (c0 > bst1) { bst1 = c0; bi1 = 12+4*c+0; }
                float c1 = w.y + Trow[12+4*c+1]; if (c1 > bst1) { bst1 = c1; bi1 = 12+4*c+1; }
                float c2 = w.z + Trow[12+4*c+2]; if (c2 > bst1) { bst1 = c2; bi1 = 12+4*c+2; }
                float c3 = w.w + Trow[12+4*c+3]; if (c3 > bst1) { bst1 = c3; bi1 = 12+4*c+3; }
            }
            {
                float4 e = E4[6+c], w = V4[6+c];
                ss2 = fmaf(Erow[24+4*c+0], e.x, ss2);
                ss2 = fmaf(Erow[24+4*c+1], e.y, ss2);
                ss2 = fmaf(Erow[24+4*c+2], e.z, ss2);
                ss2 = fmaf(Erow[24+4*c+3], e.w, ss2);
                float c0 = w.x + Trow[24+4*c+0]; if (c0 > bst2) { bst2 = c0; bi2 = 24+4*c+0; }
                float c1 = w.y + Trow[24+4*c+1]; if (c1 > bst2) { bst2 = c1; bi2 = 24+4*c+1; }
                float c2 = w.z + Trow[24+4*c+2]; if (c2 > bst2) { bst2 = c2; bi2 = 24+4*c+2; }
                float c3 = w.w + Trow[24+4*c+3]; if (c3 > bst2) { bst2 = c3; bi2 = 24+4*c+3; }
            }
            {
                float4 e = E4[9+c], w = V4[9+c];
                ss3 = fmaf(Erow[36+4*c+0], e.x, ss3);
                ss3 = fmaf(Erow[36+4*c+1], e.y, ss3);
                ss3 = fmaf(Erow[36+4*c+2], e.z, ss3);
                ss3 = fmaf(Erow[36+4*c+3], e.w, ss3);
                float c0 = w.x + Trow[36+4*c+0]; if (c0 > bst3) { bst3 = c0; bi3 = 36+4*c+0; }
                float c1 = w.y + Trow[36+4*c+1]; if (c1 > bst3) { bst3 = c1; bi3 = 36+4*c+1; }
                float c2 = w.z + Trow[36+4*c+2]; if (c2 > bst3) { bst3 = c2; bi3 = 36+4*c+2; }
                float c3 = w.w + Trow[36+4*c+3]; if (c3 > bst3) { bst3 = c3; bi3 = 36+4*c+3; }
            }
        }
        // In-order merge keeps global first-occurrence argmax on exact ties
        float best = bst0; int bi = bi0;
        if (bst1 > best) { best = bst1; bi = bi1; }
        if (bst2 > best) { best = bst2; bi = bi2; }
        if (bst3 > best) { best = bst3; bi = bi3; }
        const float ssum = (ss0 + ss1) + (ss2 + ss3);

        alpha = emit + M + __logf(ssum);   // log(0) -> -inf for START row: correct
        v     = best + emit;               // bit-identical value to reference

        bprow[(size_t)t * KK] = (unsigned char)bi;

        // Write next parity; one-step-stale normalizer W (bounded scaling)
        bufE[(q * BPB + bl) * KK + s] = __expf(alpha - W);
        bufV[(q * BPB + bl) * KK + s] = v;
        if (s == 0) { normU[q * BPB + bl] = W; normP[q * BPB + bl] = alpha; }
    }

    __syncthreads();
    // Terminal terms (reuse parity-0 buffers; loop done)
    bufE[bl * KK + s] = alpha + tstop;
    bufV[bl * KK + s] = v + tstop;
    __syncthreads();

    if (s == 0) {
        float gold = 0.0f;
        for (int i = 0; i < KK; i++) gold += gbuf[bl * KK + i];
        gold += trM[SSTOP * KK + tb[Tn - 1]];

        float mz = -INFINITY, bv = -INFINITY;
        int best_last = 0;
        for (int i = 0; i < KK; i++) {
            float az = bufE[bl * KK + i];
            float vv = bufV[bl * KK + i];
            if (az > mz) mz = az;
            if (vv > bv) { bv = vv; best_last = i; }   // first-index tie-break
        }
        float sz = 0.0f;
        for (int i = 0; i < KK; i++)
            sz += __expf(bufE[bl * KK + i] - mz);
        const float logZ = mz + __logf(sz);

        out[b]      = logZ - gold;   // nll
        out[Bn + b] = bv;            // path_score

        // Backtrace from shared-memory backpointers
        int tag = best_last;
        const unsigned char* bpb = bp + (size_t)bl * Tn * KK;
        float* pout = out + 2 * Bn + (size_t)b * Tn;
#pragma unroll 1
        for (int t = Tn - 1; t >= 0; t--) {
            pout[t] = (float)tag;
            tag = bpb[t * KK + tag];
        }
    }
}

extern "C" void kernel_launch(void* const* d_in, const int* in_sizes, int n_in,
                              void* d_out, int out_size)
{
    const float* feats = (const float*)d_in[0];
    const float* trans = (const float*)d_in[1];
    const int*   tags  = (const int*)d_in[2];
    float* out = (float*)d_out;

    cudaFuncSetAttribute(crf_fused_kernel,
                         cudaFuncAttributeMaxDynamicSharedMemorySize, SMEM_BYTES);
    crf_fused_kernel<<<NBLK, NTHREADS, SMEM_BYTES>>>(feats, trans, tags, out);
}